// round 8
// baseline (speedup 1.0000x reference)
#include <cuda_runtime.h>
#include <math.h>

// Problem constants
#define GB 8
#define GH 16
#define GN 512
#define GD 64
#define DMODEL 1024

// Scratch (device globals; allocation-free rule)
__device__ float g_qkv[3][(size_t)GB * GH * GN * GD];        // (z,b,h,n,d)
__device__ float g_geob[(size_t)GB * GH * GN * GN];          // (b,h,i,j)  log(max(g,1e-6))
__device__ float g_att[(size_t)GB * GN * GH * GD];           // (b,n,h*64+d)

// ---------------------------------------------------------------------------
// SGEMM: C[m][c] = sum_k A[m][k] * W[c][k] + bias[c]
// M=4096, N=1024, K=1024 fixed. BM=BN=128, BK=8, 256 threads, 8x8 per thread.
// PERM=1: store to (b,h,n,d) layout; PERM=0: row-major.
// ---------------------------------------------------------------------------
template <int PERM>
__device__ __forceinline__ void sgemm_body(const float* __restrict__ A,
                                           const float* __restrict__ W,
                                           const float* __restrict__ bias,
                                           float* __restrict__ C) {
    constexpr int LDS = 132;  // 128 + 4 pad: conflict-free stores & aligned float4 reads
    __shared__ float As[8 * LDS];
    __shared__ float Ws[8 * LDS];

    const int tid = threadIdx.x;
    const int tx = tid & 15;
    const int ty = tid >> 4;
    const int rowBase = blockIdx.y * 128;
    const int colBase = blockIdx.x * 128;
    const int lrow = tid >> 1;        // 0..127
    const int lk = (tid & 1) * 4;     // 0 or 4

    const float* Ag = A + (size_t)(rowBase + lrow) * 1024 + lk;
    const float* Wg = W + (size_t)(colBase + lrow) * 1024 + lk;

    float acc[8][8];
#pragma unroll
    for (int i = 0; i < 8; i++)
#pragma unroll
        for (int j = 0; j < 8; j++) acc[i][j] = 0.f;

    for (int k0 = 0; k0 < 1024; k0 += 8) {
        const float4 av = *(const float4*)(Ag + k0);
        const float4 wv = *(const float4*)(Wg + k0);
        __syncthreads();
        As[(lk + 0) * LDS + lrow] = av.x;
        As[(lk + 1) * LDS + lrow] = av.y;
        As[(lk + 2) * LDS + lrow] = av.z;
        As[(lk + 3) * LDS + lrow] = av.w;
        Ws[(lk + 0) * LDS + lrow] = wv.x;
        Ws[(lk + 1) * LDS + lrow] = wv.y;
        Ws[(lk + 2) * LDS + lrow] = wv.z;
        Ws[(lk + 3) * LDS + lrow] = wv.w;
        __syncthreads();
#pragma unroll
        for (int kk = 0; kk < 8; kk++) {
            const float4 a0 = *(const float4*)&As[kk * LDS + ty * 8];
            const float4 a1 = *(const float4*)&As[kk * LDS + ty * 8 + 4];
            const float4 b0 = *(const float4*)&Ws[kk * LDS + tx * 8];
            const float4 b1 = *(const float4*)&Ws[kk * LDS + tx * 8 + 4];
            const float ar[8] = {a0.x, a0.y, a0.z, a0.w, a1.x, a1.y, a1.z, a1.w};
            const float br[8] = {b0.x, b0.y, b0.z, b0.w, b1.x, b1.y, b1.z, b1.w};
#pragma unroll
            for (int i = 0; i < 8; i++)
#pragma unroll
                for (int j = 0; j < 8; j++)
                    acc[i][j] = fmaf(ar[i], br[j], acc[i][j]);
        }
    }

#pragma unroll
    for (int i = 0; i < 8; i++) {
        const int r = rowBase + ty * 8 + i;
#pragma unroll
        for (int j = 0; j < 8; j++) {
            const int c = colBase + tx * 8 + j;
            const float val = acc[i][j] + bias[c];
            if (PERM) {
                const int bb = r >> 9, n = r & 511;
                const int h = c >> 6, d = c & 63;
                C[(((size_t)(bb * GH + h) * GN + n) << 6) + d] = val;
            } else {
                C[(size_t)r * 1024 + c] = val;
            }
        }
    }
}

__global__ __launch_bounds__(256, 2) void qkv_gemm_kernel(
    const float* __restrict__ q, const float* __restrict__ k, const float* __restrict__ v,
    const float* __restrict__ Wq, const float* __restrict__ Wk, const float* __restrict__ Wv,
    const float* __restrict__ bq, const float* __restrict__ bk, const float* __restrict__ bv) {
    const int z = blockIdx.z;
    const float* A = (z == 0) ? q : (z == 1) ? k : v;
    const float* W = (z == 0) ? Wq : (z == 1) ? Wk : Wv;
    const float* bs = (z == 0) ? bq : (z == 1) ? bk : bv;
    sgemm_body<1>(A, W, bs, g_qkv[z]);
}

__global__ __launch_bounds__(256, 2) void out_gemm_kernel(
    const float* __restrict__ Wo, const float* __restrict__ bo, float* __restrict__ out) {
    sgemm_body<0>(g_att, Wo, bo, out);
}

// ---------------------------------------------------------------------------
// Geometry bias: g[b,h,i,j] = relu(emb(i,j) . Wg[h] + bg[h]); store log(max(g,1e-6))
// One block per (i, b); 256 threads cover j = 0..511.
// ---------------------------------------------------------------------------
__global__ __launch_bounds__(256) void geom_bias_kernel(const float* __restrict__ boxes,
                                                        const float* __restrict__ Wgm,
                                                        const float* __restrict__ bgv) {
    __shared__ float scx[512], scy[512], siw[512], sih[512], slw[512], slh[512];
    __shared__ float sW[1024];
    __shared__ float sbg[16];

    const int tid = threadIdx.x;
    const int i = blockIdx.x;
    const int b = blockIdx.y;

    for (int j = tid; j < 512; j += 256) {
        const float4 bx = *(const float4*)&boxes[((size_t)b * 512 + j) * 4];
        const float cx = (bx.x + bx.z) * 0.5f;
        const float cy = (bx.y + bx.w) * 0.5f;
        const float w = (bx.z - bx.x) + 1.0f;
        const float hh = (bx.w - bx.y) + 1.0f;
        scx[j] = cx; scy[j] = cy;
        siw[j] = w;  sih[j] = hh;
        slw[j] = __logf(w); slh[j] = __logf(hh);
    }
    for (int t = tid; t < 1024; t += 256) sW[t] = Wgm[t];
    if (tid < 16) sbg[tid] = bgv[tid];
    __syncthreads();

    const float cxi = scx[i], cyi = scy[i];
    const float inv_wi = 1.0f / siw[i], inv_hi = 1.0f / sih[i];
    const float lwi = slw[i], lhi = slh[i];

    const float dimc[8] = {1.0f, 0.421696503f, 0.177827941f, 0.0749894209f,
                           0.0316227766f, 0.0133352143f, 0.00562341325f, 0.00237137371f};

    for (int j = tid; j < 512; j += 256) {
        float pos[4];
        pos[0] = __logf(fmaxf(fabsf(cxi - scx[j]) * inv_wi, 1e-3f));
        pos[1] = __logf(fmaxf(fabsf(cyi - scy[j]) * inv_hi, 1e-3f));
        pos[2] = lwi - slw[j];
        pos[3] = lhi - slh[j];

        float acc[16];
#pragma unroll
        for (int h = 0; h < 16; h++) acc[h] = sbg[h];

#pragma unroll
        for (int p = 0; p < 4; p++) {
            const float base = 100.0f * pos[p];
#pragma unroll
            for (int f = 0; f < 8; f++) {
                float s, c;
                __sincosf(base * dimc[f], &s, &c);
                const float* wrow = &sW[p * 8 + f];
#pragma unroll
                for (int h = 0; h < 16; h++) {
                    acc[h] = fmaf(s, wrow[h * 64], acc[h]);
                    acc[h] = fmaf(c, wrow[h * 64 + 32], acc[h]);
                }
            }
        }
#pragma unroll
        for (int h = 0; h < 16; h++)
            g_geob[(((size_t)(b * GH + h) * GN + i) * GN) + j] = __logf(fmaxf(acc[h], 1e-6f));
    }
}

// ---------------------------------------------------------------------------
// Flash-style attention: per (b,h,64-query tile), stream j in 64-wide tiles
// with online softmax. smem = 4 x 64x68 floats = 69,632 B -> 3 CTAs/SM
// (24 warps/SM vs 8 before). O accumulator in registers (4x4/thread).
// ---------------------------------------------------------------------------
#define ATTN_SMEM_BYTES (4 * 64 * 68 * 4)

__global__ __launch_bounds__(256, 1) void attn_kernel() {
    extern __shared__ float sm[];
    float* sQ = sm;                  // [d][r], stride 68
    float* sK = sm + 64 * 68;        // [d][j], stride 68
    float* sV = sm + 2 * 64 * 68;    // [j][d], stride 68
    float* sP = sm + 3 * 64 * 68;    // [r][j], stride 68

    const int tid = threadIdx.x;
    const int qt = blockIdx.x, h = blockIdx.y, b = blockIdx.z;
    const int bh = b * GH + h;
    const float* qb = g_qkv[0] + ((size_t)bh * GN + qt * 64) * GD;
    const float* kb = g_qkv[1] + (size_t)bh * GN * GD;
    const float* vb = g_qkv[2] + (size_t)bh * GN * GD;
    const float* gb = g_geob + ((size_t)bh * GN + qt * 64) * GN;

    // Load Q tile transposed
#pragma unroll 4
    for (int t = tid; t < 4096; t += 256) {
        const int r = t >> 6, d = t & 63;
        sQ[d * 68 + r] = qb[t];
    }

    const int tx = tid & 15;   // 4 j-cols / d-cols
    const int ty = tid >> 4;   // 4 rows

    float mrow[4], lrow[4], o4[4][4];
#pragma unroll
    for (int i = 0; i < 4; i++) {
        mrow[i] = -1e30f;
        lrow[i] = 0.f;
#pragma unroll
        for (int j = 0; j < 4; j++) o4[i][j] = 0.f;
    }

    for (int jt = 0; jt < 8; jt++) {
        __syncthreads();   // previous PV done before overwriting sK/sV; prev sP reads done
#pragma unroll 4
        for (int t = tid; t < 4096; t += 256) {
            const int r = t >> 6, d = t & 63;
            sK[d * 68 + r] = kb[jt * 4096 + t];
        }
#pragma unroll 4
        for (int t = tid; t < 4096; t += 256) {
            const int r = t >> 6, d = t & 63;
            sV[r * 68 + d] = vb[jt * 4096 + t];
        }
        __syncthreads();

        // s = Q K^T for this tile
        float acc[4][4];
#pragma unroll
        for (int i = 0; i < 4; i++)
#pragma unroll
            for (int j = 0; j < 4; j++) acc[i][j] = 0.f;
#pragma unroll
        for (int d = 0; d < 64; d++) {
            const float4 a = *(const float4*)&sQ[d * 68 + ty * 4];
            const float4 kv = *(const float4*)&sK[d * 68 + tx * 4];
            const float ar[4] = {a.x, a.y, a.z, a.w};
            const float br[4] = {kv.x, kv.y, kv.z, kv.w};
#pragma unroll
            for (int i = 0; i < 4; i++)
#pragma unroll
                for (int j = 0; j < 4; j++)
                    acc[i][j] = fmaf(ar[i], br[j], acc[i][j]);
        }

        // s = s/8 + bias; online softmax update
#pragma unroll
        for (int i = 0; i < 4; i++) {
            const int r = ty * 4 + i;
            const float4 b4 = *(const float4*)&gb[(size_t)r * GN + jt * 64 + tx * 4];
            float s0 = fmaf(acc[i][0], 0.125f, b4.x);
            float s1 = fmaf(acc[i][1], 0.125f, b4.y);
            float s2 = fmaf(acc[i][2], 0.125f, b4.z);
            float s3 = fmaf(acc[i][3], 0.125f, b4.w);

            float tmax = fmaxf(fmaxf(s0, s1), fmaxf(s2, s3));
#pragma unroll
            for (int o = 8; o > 0; o >>= 1)
                tmax = fmaxf(tmax, __shfl_xor_sync(0xffffffffu, tmax, o));
            const float m_new = fmaxf(mrow[i], tmax);
            const float scale = __expf(mrow[i] - m_new);
            mrow[i] = m_new;

            const float p0 = __expf(s0 - m_new);
            const float p1 = __expf(s1 - m_new);
            const float p2 = __expf(s2 - m_new);
            const float p3 = __expf(s3 - m_new);
            float tsum = p0 + p1 + p2 + p3;
#pragma unroll
            for (int o = 8; o > 0; o >>= 1)
                tsum += __shfl_xor_sync(0xffffffffu, tsum, o);
            lrow[i] = lrow[i] * scale + tsum;

#pragma unroll
            for (int j = 0; j < 4; j++) o4[i][j] *= scale;

            float* prow = &sP[r * 68 + tx * 4];
            prow[0] = p0; prow[1] = p1; prow[2] = p2; prow[3] = p3;
        }
        __syncthreads();

        // O += P V  (this tile)
#pragma unroll
        for (int kk = 0; kk < 64; kk++) {
            const float4 vv = *(const float4*)&sV[kk * 68 + tx * 4];
            const float pr[4] = {sP[(ty * 4 + 0) * 68 + kk],
                                 sP[(ty * 4 + 1) * 68 + kk],
                                 sP[(ty * 4 + 2) * 68 + kk],
                                 sP[(ty * 4 + 3) * 68 + kk]};
            const float vr[4] = {vv.x, vv.y, vv.z, vv.w};
#pragma unroll
            for (int i = 0; i < 4; i++)
#pragma unroll
                for (int j = 0; j < 4; j++)
                    o4[i][j] = fmaf(pr[i], vr[j], o4[i][j]);
        }
    }

    // Normalize and store to (b, n, h*64+d)
#pragma unroll
    for (int i = 0; i < 4; i++) {
        const float inv = 1.0f / lrow[i];
        const int n = qt * 64 + ty * 4 + i;
        float4 res;
        res.x = o4[i][0] * inv; res.y = o4[i][1] * inv;
        res.z = o4[i][2] * inv; res.w = o4[i][3] * inv;
        *(float4*)&g_att[((size_t)b * GN + n) * 1024 + h * 64 + tx * 4] = res;
    }
}

// ---------------------------------------------------------------------------
extern "C" void kernel_launch(void* const* d_in, const int* in_sizes, int n_in,
                              void* d_out, int out_size) {
    (void)in_sizes; (void)n_in; (void)out_size;
    const float* queries = (const float*)d_in[0];
    const float* keys    = (const float*)d_in[1];
    const float* values  = (const float*)d_in[2];
    const float* boxes   = (const float*)d_in[3];
    const float* Wq = (const float*)d_in[4];
    const float* bq = (const float*)d_in[5];
    const float* Wk = (const float*)d_in[6];
    const float* bk = (const float*)d_in[7];
    const float* Wv = (const float*)d_in[8];
    const float* bv = (const float*)d_in[9];
    const float* Wo = (const float*)d_in[10];
    const float* bo = (const float*)d_in[11];
    const float* Wg = (const float*)d_in[12];
    const float* bg = (const float*)d_in[13];
    float* out = (float*)d_out;

    cudaFuncSetAttribute(attn_kernel, cudaFuncAttributeMaxDynamicSharedMemorySize,
                         ATTN_SMEM_BYTES);

    qkv_gemm_kernel<<<dim3(8, 32, 3), 256>>>(queries, keys, values, Wq, Wk, Wv, bq, bk, bv);
    geom_bias_kernel<<<dim3(512, 8), 256>>>(boxes, Wg, bg);
    attn_kernel<<<dim3(8, 16, 8), 256, ATTN_SMEM_BYTES>>>();
    out_gemm_kernel<<<dim3(8, 32, 1), 256>>>(Wo, bo, out);
}

// round 9
// speedup vs baseline: 1.0129x; 1.0129x over previous
#include <cuda_runtime.h>
#include <math.h>

// Problem constants
#define GB 8
#define GH 16
#define GN 512
#define GD 64
#define DMODEL 1024

// Scratch (device globals; allocation-free rule)
__device__ float g_qkv[3][(size_t)GB * GH * GN * GD];        // (z,b,h,n,d)
__device__ float g_geob[(size_t)GB * GH * GN * GN];          // (b,h,i,j)  log(max(g,1e-6))
__device__ float g_att[(size_t)GB * GN * GH * GD];           // (b,n,h*64+d)

// ---------------------------------------------------------------------------
// SGEMM: C[m][c] = sum_k A[m][k] * W[c][k] + bias[c]
// M=4096, N=1024, K=1024. BM=BN=128, BK=8, 256 threads, 8x8 per thread.
// Software-pipelined ping-pong smem: branchless clamped prefetch, manual
// 2-unroll, ONE __syncthreads per K-chunk. (R2's failed version used a
// predicated guard in a dynamic loop + 2 syncs — root cause of its regression.)
// PERM=1: store to (b,h,n,d) layout; PERM=0: row-major.
// ---------------------------------------------------------------------------
template <int PERM>
__device__ __forceinline__ void sgemm_body(const float* __restrict__ A,
                                           const float* __restrict__ W,
                                           const float* __restrict__ bias,
                                           float* __restrict__ C) {
    constexpr int LDS = 132;  // 128 + 4 pad
    __shared__ float As[2][8 * LDS];
    __shared__ float Ws[2][8 * LDS];

    const int tid = threadIdx.x;
    const int tx = tid & 15;
    const int ty = tid >> 4;
    const int rowBase = blockIdx.y * 128;
    const int colBase = blockIdx.x * 128;
    const int lrow = tid >> 1;        // 0..127
    const int lk = (tid & 1) * 4;     // 0 or 4

    const float* Ag = A + (size_t)(rowBase + lrow) * 1024 + lk;
    const float* Wg = W + (size_t)(colBase + lrow) * 1024 + lk;

    float acc[8][8];
#pragma unroll
    for (int i = 0; i < 8; i++)
#pragma unroll
        for (int j = 0; j < 8; j++) acc[i][j] = 0.f;

#define SGEMM_STS(buf, a4, w4)                        \
    As[buf][(lk + 0) * LDS + lrow] = a4.x;            \
    As[buf][(lk + 1) * LDS + lrow] = a4.y;            \
    As[buf][(lk + 2) * LDS + lrow] = a4.z;            \
    As[buf][(lk + 3) * LDS + lrow] = a4.w;            \
    Ws[buf][(lk + 0) * LDS + lrow] = w4.x;            \
    Ws[buf][(lk + 1) * LDS + lrow] = w4.y;            \
    Ws[buf][(lk + 2) * LDS + lrow] = w4.z;            \
    Ws[buf][(lk + 3) * LDS + lrow] = w4.w;

#define SGEMM_FFMA(buf)                                                        \
    _Pragma("unroll")                                                          \
    for (int kk = 0; kk < 8; kk++) {                                           \
        const float4 a0 = *(const float4*)&As[buf][kk * LDS + ty * 8];         \
        const float4 a1 = *(const float4*)&As[buf][kk * LDS + ty * 8 + 4];     \
        const float4 b0 = *(const float4*)&Ws[buf][kk * LDS + tx * 8];         \
        const float4 b1 = *(const float4*)&Ws[buf][kk * LDS + tx * 8 + 4];     \
        const float ar[8] = {a0.x, a0.y, a0.z, a0.w, a1.x, a1.y, a1.z, a1.w};  \
        const float br[8] = {b0.x, b0.y, b0.z, b0.w, b1.x, b1.y, b1.z, b1.w};  \
        _Pragma("unroll")                                                      \
        for (int i = 0; i < 8; i++)                                            \
            _Pragma("unroll")                                                  \
            for (int j = 0; j < 8; j++)                                        \
                acc[i][j] = fmaf(ar[i], br[j], acc[i][j]);                     \
    }

    // prefetch chunk 0
    float4 av = *(const float4*)(Ag);
    float4 wv = *(const float4*)(Wg);

#pragma unroll 1
    for (int c = 0; c < 128; c += 2) {
        // even phase: buffer 0
        SGEMM_STS(0, av, wv)
        {
            const int kn = (c + 1 < 127 ? c + 1 : 127) * 8;  // branchless clamp
            av = *(const float4*)(Ag + kn);
            wv = *(const float4*)(Wg + kn);
        }
        __syncthreads();
        SGEMM_FFMA(0)

        // odd phase: buffer 1
        SGEMM_STS(1, av, wv)
        {
            const int kn = (c + 2 < 127 ? c + 2 : 127) * 8;
            av = *(const float4*)(Ag + kn);
            wv = *(const float4*)(Wg + kn);
        }
        __syncthreads();
        SGEMM_FFMA(1)
    }
#undef SGEMM_STS
#undef SGEMM_FFMA

#pragma unroll
    for (int i = 0; i < 8; i++) {
        const int r = rowBase + ty * 8 + i;
#pragma unroll
        for (int j = 0; j < 8; j++) {
            const int c = colBase + tx * 8 + j;
            const float val = acc[i][j] + bias[c];
            if (PERM) {
                const int bb = r >> 9, n = r & 511;
                const int h = c >> 6, d = c & 63;
                C[(((size_t)(bb * GH + h) * GN + n) << 6) + d] = val;
            } else {
                C[(size_t)r * 1024 + c] = val;
            }
        }
    }
}

__global__ __launch_bounds__(256, 2) void qkv_gemm_kernel(
    const float* __restrict__ q, const float* __restrict__ k, const float* __restrict__ v,
    const float* __restrict__ Wq, const float* __restrict__ Wk, const float* __restrict__ Wv,
    const float* __restrict__ bq, const float* __restrict__ bk, const float* __restrict__ bv) {
    const int z = blockIdx.z;
    const float* A = (z == 0) ? q : (z == 1) ? k : v;
    const float* W = (z == 0) ? Wq : (z == 1) ? Wk : Wv;
    const float* bs = (z == 0) ? bq : (z == 1) ? bk : bv;
    sgemm_body<1>(A, W, bs, g_qkv[z]);
}

__global__ __launch_bounds__(256, 2) void out_gemm_kernel(
    const float* __restrict__ Wo, const float* __restrict__ bo, float* __restrict__ out) {
    sgemm_body<0>(g_att, Wo, bo, out);
}

// ---------------------------------------------------------------------------
// Geometry bias: g[b,h,i,j] = relu(emb(i,j) . Wg[h] + bg[h]); store log(max(g,1e-6))
// One block per (i, b); 256 threads cover j = 0..511.  (unchanged)
// ---------------------------------------------------------------------------
__global__ __launch_bounds__(256) void geom_bias_kernel(const float* __restrict__ boxes,
                                                        const float* __restrict__ Wgm,
                                                        const float* __restrict__ bgv) {
    __shared__ float scx[512], scy[512], siw[512], sih[512], slw[512], slh[512];
    __shared__ float sW[1024];
    __shared__ float sbg[16];

    const int tid = threadIdx.x;
    const int i = blockIdx.x;
    const int b = blockIdx.y;

    for (int j = tid; j < 512; j += 256) {
        const float4 bx = *(const float4*)&boxes[((size_t)b * 512 + j) * 4];
        const float cx = (bx.x + bx.z) * 0.5f;
        const float cy = (bx.y + bx.w) * 0.5f;
        const float w = (bx.z - bx.x) + 1.0f;
        const float hh = (bx.w - bx.y) + 1.0f;
        scx[j] = cx; scy[j] = cy;
        siw[j] = w;  sih[j] = hh;
        slw[j] = __logf(w); slh[j] = __logf(hh);
    }
    for (int t = tid; t < 1024; t += 256) sW[t] = Wgm[t];
    if (tid < 16) sbg[tid] = bgv[tid];
    __syncthreads();

    const float cxi = scx[i], cyi = scy[i];
    const float inv_wi = 1.0f / siw[i], inv_hi = 1.0f / sih[i];
    const float lwi = slw[i], lhi = slh[i];

    const float dimc[8] = {1.0f, 0.421696503f, 0.177827941f, 0.0749894209f,
                           0.0316227766f, 0.0133352143f, 0.00562341325f, 0.00237137371f};

    for (int j = tid; j < 512; j += 256) {
        float pos[4];
        pos[0] = __logf(fmaxf(fabsf(cxi - scx[j]) * inv_wi, 1e-3f));
        pos[1] = __logf(fmaxf(fabsf(cyi - scy[j]) * inv_hi, 1e-3f));
        pos[2] = lwi - slw[j];
        pos[3] = lhi - slh[j];

        float acc[16];
#pragma unroll
        for (int h = 0; h < 16; h++) acc[h] = sbg[h];

#pragma unroll
        for (int p = 0; p < 4; p++) {
            const float base = 100.0f * pos[p];
#pragma unroll
            for (int f = 0; f < 8; f++) {
                float s, c;
                __sincosf(base * dimc[f], &s, &c);
                const float* wrow = &sW[p * 8 + f];
#pragma unroll
                for (int h = 0; h < 16; h++) {
                    acc[h] = fmaf(s, wrow[h * 64], acc[h]);
                    acc[h] = fmaf(c, wrow[h * 64 + 32], acc[h]);
                }
            }
        }
#pragma unroll
        for (int h = 0; h < 16; h++)
            g_geob[(((size_t)(b * GH + h) * GN + i) * GN) + j] = __logf(fmaxf(acc[h], 1e-6f));
    }
}

// ---------------------------------------------------------------------------
// Flash-style attention, online softmax. smem = 4 x 64x68 floats = 69,632 B.
// __launch_bounds__(256, 3): cap regs at 85 so 3 CTAs/SM actually materialize
// (208.9 KB smem <= 228 KB). R8's (256,1) allowed ptxas to blow the reg budget
// and stay occupancy-starved.
// ---------------------------------------------------------------------------
#define ATTN_SMEM_BYTES (4 * 64 * 68 * 4)

__global__ __launch_bounds__(256, 3) void attn_kernel() {
    extern __shared__ float sm[];
    float* sQ = sm;                  // [d][r], stride 68
    float* sK = sm + 64 * 68;        // [d][j], stride 68
    float* sV = sm + 2 * 64 * 68;    // [j][d], stride 68
    float* sP = sm + 3 * 64 * 68;    // [r][j], stride 68

    const int tid = threadIdx.x;
    const int qt = blockIdx.x, h = blockIdx.y, b = blockIdx.z;
    const int bh = b * GH + h;
    const float* qb = g_qkv[0] + ((size_t)bh * GN + qt * 64) * GD;
    const float* kb = g_qkv[1] + (size_t)bh * GN * GD;
    const float* vb = g_qkv[2] + (size_t)bh * GN * GD;
    const float* gb = g_geob + ((size_t)bh * GN + qt * 64) * GN;

    // Load Q tile transposed
#pragma unroll 4
    for (int t = tid; t < 4096; t += 256) {
        const int r = t >> 6, d = t & 63;
        sQ[d * 68 + r] = qb[t];
    }

    const int tx = tid & 15;   // 4 j-cols / d-cols
    const int ty = tid >> 4;   // 4 rows

    float mrow[4], lrow[4], o4[4][4];
#pragma unroll
    for (int i = 0; i < 4; i++) {
        mrow[i] = -1e30f;
        lrow[i] = 0.f;
#pragma unroll
        for (int j = 0; j < 4; j++) o4[i][j] = 0.f;
    }

    for (int jt = 0; jt < 8; jt++) {
        __syncthreads();   // prev PV done before overwriting sK/sV; prev sP reads done
#pragma unroll 4
        for (int t = tid; t < 4096; t += 256) {
            const int r = t >> 6, d = t & 63;
            sK[d * 68 + r] = kb[jt * 4096 + t];
        }
#pragma unroll 4
        for (int t = tid; t < 4096; t += 256) {
            const int r = t >> 6, d = t & 63;
            sV[r * 68 + d] = vb[jt * 4096 + t];
        }
        __syncthreads();

        // s = Q K^T for this tile
        float acc[4][4];
#pragma unroll
        for (int i = 0; i < 4; i++)
#pragma unroll
            for (int j = 0; j < 4; j++) acc[i][j] = 0.f;
#pragma unroll
        for (int d = 0; d < 64; d++) {
            const float4 a = *(const float4*)&sQ[d * 68 + ty * 4];
            const float4 kv = *(const float4*)&sK[d * 68 + tx * 4];
            const float ar[4] = {a.x, a.y, a.z, a.w};
            const float br[4] = {kv.x, kv.y, kv.z, kv.w};
#pragma unroll
            for (int i = 0; i < 4; i++)
#pragma unroll
                for (int j = 0; j < 4; j++)
                    acc[i][j] = fmaf(ar[i], br[j], acc[i][j]);
        }

        // s = s/8 + bias; online softmax update
#pragma unroll
        for (int i = 0; i < 4; i++) {
            const int r = ty * 4 + i;
            const float4 b4 = *(const float4*)&gb[(size_t)r * GN + jt * 64 + tx * 4];
            float s0 = fmaf(acc[i][0], 0.125f, b4.x);
            float s1 = fmaf(acc[i][1], 0.125f, b4.y);
            float s2 = fmaf(acc[i][2], 0.125f, b4.z);
            float s3 = fmaf(acc[i][3], 0.125f, b4.w);

            float tmax = fmaxf(fmaxf(s0, s1), fmaxf(s2, s3));
#pragma unroll
            for (int o = 8; o > 0; o >>= 1)
                tmax = fmaxf(tmax, __shfl_xor_sync(0xffffffffu, tmax, o));
            const float m_new = fmaxf(mrow[i], tmax);
            const float scale = __expf(mrow[i] - m_new);
            mrow[i] = m_new;

            const float p0 = __expf(s0 - m_new);
            const float p1 = __expf(s1 - m_new);
            const float p2 = __expf(s2 - m_new);
            const float p3 = __expf(s3 - m_new);
            float tsum = p0 + p1 + p2 + p3;
#pragma unroll
            for (int o = 8; o > 0; o >>= 1)
                tsum += __shfl_xor_sync(0xffffffffu, tsum, o);
            lrow[i] = lrow[i] * scale + tsum;

#pragma unroll
            for (int j = 0; j < 4; j++) o4[i][j] *= scale;

            float* prow = &sP[r * 68 + tx * 4];
            prow[0] = p0; prow[1] = p1; prow[2] = p2; prow[3] = p3;
        }
        __syncthreads();

        // O += P V  (this tile)
#pragma unroll
        for (int kk = 0; kk < 64; kk++) {
            const float4 vv = *(const float4*)&sV[kk * 68 + tx * 4];
            const float pr[4] = {sP[(ty * 4 + 0) * 68 + kk],
                                 sP[(ty * 4 + 1) * 68 + kk],
                                 sP[(ty * 4 + 2) * 68 + kk],
                                 sP[(ty * 4 + 3) * 68 + kk]};
            const float vr[4] = {vv.x, vv.y, vv.z, vv.w};
#pragma unroll
            for (int i = 0; i < 4; i++)
#pragma unroll
                for (int j = 0; j < 4; j++)
                    o4[i][j] = fmaf(pr[i], vr[j], o4[i][j]);
        }
    }

    // Normalize and store to (b, n, h*64+d)
#pragma unroll
    for (int i = 0; i < 4; i++) {
        const float inv = 1.0f / lrow[i];
        const int n = qt * 64 + ty * 4 + i;
        float4 res;
        res.x = o4[i][0] * inv; res.y = o4[i][1] * inv;
        res.z = o4[i][2] * inv; res.w = o4[i][3] * inv;
        *(float4*)&g_att[((size_t)b * GN + n) * 1024 + h * 64 + tx * 4] = res;
    }
}

// ---------------------------------------------------------------------------
extern "C" void kernel_launch(void* const* d_in, const int* in_sizes, int n_in,
                              void* d_out, int out_size) {
    (void)in_sizes; (void)n_in; (void)out_size;
    const float* queries = (const float*)d_in[0];
    const float* keys    = (const float*)d_in[1];
    const float* values  = (const float*)d_in[2];
    const float* boxes   = (const float*)d_in[3];
    const float* Wq = (const float*)d_in[4];
    const float* bq = (const float*)d_in[5];
    const float* Wk = (const float*)d_in[6];
    const float* bk = (const float*)d_in[7];
    const float* Wv = (const float*)d_in[8];
    const float* bv = (const float*)d_in[9];
    const float* Wo = (const float*)d_in[10];
    const float* bo = (const float*)d_in[11];
    const float* Wg = (const float*)d_in[12];
    const float* bg = (const float*)d_in[13];
    float* out = (float*)d_out;

    cudaFuncSetAttribute(attn_kernel, cudaFuncAttributeMaxDynamicSharedMemorySize,
                         ATTN_SMEM_BYTES);

    qkv_gemm_kernel<<<dim3(8, 32, 3), 256>>>(queries, keys, values, Wq, Wk, Wv, bq, bk, bv);
    geom_bias_kernel<<<dim3(512, 8), 256>>>(boxes, Wg, bg);
    attn_kernel<<<dim3(8, 16, 8), 256, ATTN_SMEM_BYTES>>>();
    out_gemm_kernel<<<dim3(8, 32, 1), 256>>>(Wo, bo, out);
}

// round 11
// speedup vs baseline: 1.8998x; 1.8757x over previous
#include <cuda_runtime.h>
#include <math.h>

// Problem constants
#define GB 8
#define GH 16
#define GN 512
#define GD 64
#define DMODEL 1024

// Scratch (device globals; allocation-free rule)
__device__ float g_qkv[3][(size_t)GB * GH * GN * GD];        // (z,b,h,n,d)
__device__ float g_geob[(size_t)GB * GH * GN * GN];          // (b,h,i,j)  log(max(g,1e-6))
__device__ float g_att[(size_t)GB * GN * GH * GD];           // (b,n,h*64+d)

// ---------------------------------------------------------------------------
// SGEMM (R9 version — pipelined ping-pong, one sync per chunk)
// ---------------------------------------------------------------------------
template <int PERM>
__device__ __forceinline__ void sgemm_body(const float* __restrict__ A,
                                           const float* __restrict__ W,
                                           const float* __restrict__ bias,
                                           float* __restrict__ C) {
    constexpr int LDS = 132;  // 128 + 4 pad
    __shared__ float As[2][8 * LDS];
    __shared__ float Ws[2][8 * LDS];

    const int tid = threadIdx.x;
    const int tx = tid & 15;
    const int ty = tid >> 4;
    const int rowBase = blockIdx.y * 128;
    const int colBase = blockIdx.x * 128;
    const int lrow = tid >> 1;        // 0..127
    const int lk = (tid & 1) * 4;     // 0 or 4

    const float* Ag = A + (size_t)(rowBase + lrow) * 1024 + lk;
    const float* Wg = W + (size_t)(colBase + lrow) * 1024 + lk;

    float acc[8][8];
#pragma unroll
    for (int i = 0; i < 8; i++)
#pragma unroll
        for (int j = 0; j < 8; j++) acc[i][j] = 0.f;

#define SGEMM_STS(buf, a4, w4)                        \
    As[buf][(lk + 0) * LDS + lrow] = a4.x;            \
    As[buf][(lk + 1) * LDS + lrow] = a4.y;            \
    As[buf][(lk + 2) * LDS + lrow] = a4.z;            \
    As[buf][(lk + 3) * LDS + lrow] = a4.w;            \
    Ws[buf][(lk + 0) * LDS + lrow] = w4.x;            \
    Ws[buf][(lk + 1) * LDS + lrow] = w4.y;            \
    Ws[buf][(lk + 2) * LDS + lrow] = w4.z;            \
    Ws[buf][(lk + 3) * LDS + lrow] = w4.w;

#define SGEMM_FFMA(buf)                                                        \
    _Pragma("unroll")                                                          \
    for (int kk = 0; kk < 8; kk++) {                                           \
        const float4 a0 = *(const float4*)&As[buf][kk * LDS + ty * 8];         \
        const float4 a1 = *(const float4*)&As[buf][kk * LDS + ty * 8 + 4];     \
        const float4 b0 = *(const float4*)&Ws[buf][kk * LDS + tx * 8];         \
        const float4 b1 = *(const float4*)&Ws[buf][kk * LDS + tx * 8 + 4];     \
        const float ar[8] = {a0.x, a0.y, a0.z, a0.w, a1.x, a1.y, a1.z, a1.w};  \
        const float br[8] = {b0.x, b0.y, b0.z, b0.w, b1.x, b1.y, b1.z, b1.w};  \
        _Pragma("unroll")                                                      \
        for (int i = 0; i < 8; i++)                                            \
            _Pragma("unroll")                                                  \
            for (int j = 0; j < 8; j++)                                        \
                acc[i][j] = fmaf(ar[i], br[j], acc[i][j]);                     \
    }

    // prefetch chunk 0
    float4 av = *(const float4*)(Ag);
    float4 wv = *(const float4*)(Wg);

#pragma unroll 1
    for (int c = 0; c < 128; c += 2) {
        SGEMM_STS(0, av, wv)
        {
            const int kn = (c + 1 < 127 ? c + 1 : 127) * 8;
            av = *(const float4*)(Ag + kn);
            wv = *(const float4*)(Wg + kn);
        }
        __syncthreads();
        SGEMM_FFMA(0)

        SGEMM_STS(1, av, wv)
        {
            const int kn = (c + 2 < 127 ? c + 2 : 127) * 8;
            av = *(const float4*)(Ag + kn);
            wv = *(const float4*)(Wg + kn);
        }
        __syncthreads();
        SGEMM_FFMA(1)
    }
#undef SGEMM_STS
#undef SGEMM_FFMA

#pragma unroll
    for (int i = 0; i < 8; i++) {
        const int r = rowBase + ty * 8 + i;
#pragma unroll
        for (int j = 0; j < 8; j++) {
            const int c = colBase + tx * 8 + j;
            const float val = acc[i][j] + bias[c];
            if (PERM) {
                const int bb = r >> 9, n = r & 511;
                const int h = c >> 6, d = c & 63;
                C[(((size_t)(bb * GH + h) * GN + n) << 6) + d] = val;
            } else {
                C[(size_t)r * 1024 + c] = val;
            }
        }
    }
}

__global__ __launch_bounds__(256, 2) void qkv_gemm_kernel(
    const float* __restrict__ q, const float* __restrict__ k, const float* __restrict__ v,
    const float* __restrict__ Wq, const float* __restrict__ Wk, const float* __restrict__ Wv,
    const float* __restrict__ bq, const float* __restrict__ bk, const float* __restrict__ bv) {
    const int z = blockIdx.z;
    const float* A = (z == 0) ? q : (z == 1) ? k : v;
    const float* W = (z == 0) ? Wq : (z == 1) ? Wk : Wv;
    const float* bs = (z == 0) ? bq : (z == 1) ? bk : bv;
    sgemm_body<1>(A, W, bs, g_qkv[z]);
}

__global__ __launch_bounds__(256, 2) void out_gemm_kernel(
    const float* __restrict__ Wo, const float* __restrict__ bo, float* __restrict__ out) {
    sgemm_body<0>(g_att, Wo, bo, out);
}

// ---------------------------------------------------------------------------
// Geometry bias, register-tiled: each thread owns 4 j-values x 16 heads.
// LDS/FMA drops 1.0 -> 0.125 (weights broadcast once per (p,f) for 4 j's).
// Block: 256 threads = 2 i-values x 128 threads; each thread: j, j+128, +256, +384.
// Grid: (256, 8).
// ---------------------------------------------------------------------------
__global__ __launch_bounds__(256, 2) void geom_bias_kernel(const float* __restrict__ boxes,
                                                           const float* __restrict__ Wgm,
                                                           const float* __restrict__ bgv) {
    __shared__ float scx[512], scy[512], siw[512], sih[512], slw[512], slh[512];
    __shared__ float2 sW2[512];   // [(p*8+f)*16 + h] = (W_sin, W_cos)
    __shared__ float sbg[16];

    const int tid = threadIdx.x;
    const int b = blockIdx.y;
    const int i = blockIdx.x * 2 + (tid >> 7);   // 2 i's per block
    const int jt = tid & 127;                    // base j; handles jt + {0,128,256,384}

    for (int j = tid; j < 512; j += 256) {
        const float4 bx = *(const float4*)&boxes[((size_t)b * 512 + j) * 4];
        const float cx = (bx.x + bx.z) * 0.5f;
        const float cy = (bx.y + bx.w) * 0.5f;
        const float w = (bx.z - bx.x) + 1.0f;
        const float hh = (bx.w - bx.y) + 1.0f;
        scx[j] = cx; scy[j] = cy;
        siw[j] = w;  sih[j] = hh;
        slw[j] = __logf(w); slh[j] = __logf(hh);
    }
    for (int t = tid; t < 512; t += 256) {
        const int pf = t >> 4, h = t & 15;
        sW2[t] = make_float2(Wgm[h * 64 + pf], Wgm[h * 64 + 32 + pf]);
    }
    if (tid < 16) sbg[tid] = bgv[tid];
    __syncthreads();

    const float cxi = scx[i], cyi = scy[i];
    const float inv_wi = 1.0f / siw[i], inv_hi = 1.0f / sih[i];
    const float lwi = slw[i], lhi = slh[i];

    const float dimc[8] = {1.0f, 0.421696503f, 0.177827941f, 0.0749894209f,
                           0.0316227766f, 0.0133352143f, 0.00562341325f, 0.00237137371f};

    // pos components for the 4 owned j's
    float pos[4][4];
#pragma unroll
    for (int jj = 0; jj < 4; jj++) {
        const int j = jt + jj * 128;
        pos[0][jj] = __logf(fmaxf(fabsf(cxi - scx[j]) * inv_wi, 1e-3f));
        pos[1][jj] = __logf(fmaxf(fabsf(cyi - scy[j]) * inv_hi, 1e-3f));
        pos[2][jj] = lwi - slw[j];
        pos[3][jj] = lhi - slh[j];
    }

    float acc[4][16];
#pragma unroll
    for (int jj = 0; jj < 4; jj++)
#pragma unroll
        for (int h = 0; h < 16; h++) acc[jj][h] = sbg[h];

#pragma unroll
    for (int p = 0; p < 4; p++) {
#pragma unroll
        for (int f = 0; f < 8; f++) {
            float s[4], c[4];
#pragma unroll
            for (int jj = 0; jj < 4; jj++)
                __sincosf(100.0f * pos[p][jj] * dimc[f], &s[jj], &c[jj]);
            const float2* wrow = &sW2[(p * 8 + f) * 16];
#pragma unroll
            for (int h = 0; h < 16; h++) {
                const float2 w2 = wrow[h];   // broadcast across warp
#pragma unroll
                for (int jj = 0; jj < 4; jj++)
                    acc[jj][h] = fmaf(s[jj], w2.x, fmaf(c[jj], w2.y, acc[jj][h]));
            }
        }
    }

#pragma unroll
    for (int h = 0; h < 16; h++) {
        float* dst = &g_geob[(((size_t)(b * GH + h) * GN + i) * GN) + jt];
#pragma unroll
        for (int jj = 0; jj < 4; jj++)
            dst[jj * 128] = __logf(fmaxf(acc[jj][h], 1e-6f));
    }
}

// ---------------------------------------------------------------------------
// Flash-style attention, online softmax (R9 version, unchanged).
// smem = 4 x 64x68 floats = 69,632 B; __launch_bounds__(256, 3).
// ---------------------------------------------------------------------------
#define ATTN_SMEM_BYTES (4 * 64 * 68 * 4)

__global__ __launch_bounds__(256, 3) void attn_kernel() {
    extern __shared__ float sm[];
    float* sQ = sm;                  // [d][r], stride 68
    float* sK = sm + 64 * 68;        // [d][j], stride 68
    float* sV = sm + 2 * 64 * 68;    // [j][d], stride 68
    float* sP = sm + 3 * 64 * 68;    // [r][j], stride 68

    const int tid = threadIdx.x;
    const int qt = blockIdx.x, h = blockIdx.y, b = blockIdx.z;
    const int bh = b * GH + h;
    const float* qb = g_qkv[0] + ((size_t)bh * GN + qt * 64) * GD;
    const float* kb = g_qkv[1] + (size_t)bh * GN * GD;
    const float* vb = g_qkv[2] + (size_t)bh * GN * GD;
    const float* gb = g_geob + ((size_t)bh * GN + qt * 64) * GN;

#pragma unroll 4
    for (int t = tid; t < 4096; t += 256) {
        const int r = t >> 6, d = t & 63;
        sQ[d * 68 + r] = qb[t];
    }

    const int tx = tid & 15;
    const int ty = tid >> 4;

    float mrow[4], lrow[4], o4[4][4];
#pragma unroll
    for (int i = 0; i < 4; i++) {
        mrow[i] = -1e30f;
        lrow[i] = 0.f;
#pragma unroll
        for (int j = 0; j < 4; j++) o4[i][j] = 0.f;
    }

    for (int jt = 0; jt < 8; jt++) {
        __syncthreads();
#pragma unroll 4
        for (int t = tid; t < 4096; t += 256) {
            const int r = t >> 6, d = t & 63;
            sK[d * 68 + r] = kb[jt * 4096 + t];
        }
#pragma unroll 4
        for (int t = tid; t < 4096; t += 256) {
            const int r = t >> 6, d = t & 63;
            sV[r * 68 + d] = vb[jt * 4096 + t];
        }
        __syncthreads();

        float acc[4][4];
#pragma unroll
        for (int i = 0; i < 4; i++)
#pragma unroll
            for (int j = 0; j < 4; j++) acc[i][j] = 0.f;
#pragma unroll
        for (int d = 0; d < 64; d++) {
            const float4 a = *(const float4*)&sQ[d * 68 + ty * 4];
            const float4 kv = *(const float4*)&sK[d * 68 + tx * 4];
            const float ar[4] = {a.x, a.y, a.z, a.w};
            const float br[4] = {kv.x, kv.y, kv.z, kv.w};
#pragma unroll
            for (int i = 0; i < 4; i++)
#pragma unroll
                for (int j = 0; j < 4; j++)
                    acc[i][j] = fmaf(ar[i], br[j], acc[i][j]);
        }

#pragma unroll
        for (int i = 0; i < 4; i++) {
            const int r = ty * 4 + i;
            const float4 b4 = *(const float4*)&gb[(size_t)r * GN + jt * 64 + tx * 4];
            float s0 = fmaf(acc[i][0], 0.125f, b4.x);
            float s1 = fmaf(acc[i][1], 0.125f, b4.y);
            float s2 = fmaf(acc[i][2], 0.125f, b4.z);
            float s3 = fmaf(acc[i][3], 0.125f, b4.w);

            float tmax = fmaxf(fmaxf(s0, s1), fmaxf(s2, s3));
#pragma unroll
            for (int o = 8; o > 0; o >>= 1)
                tmax = fmaxf(tmax, __shfl_xor_sync(0xffffffffu, tmax, o));
            const float m_new = fmaxf(mrow[i], tmax);
            const float scale = __expf(mrow[i] - m_new);
            mrow[i] = m_new;

            const float p0 = __expf(s0 - m_new);
            const float p1 = __expf(s1 - m_new);
            const float p2 = __expf(s2 - m_new);
            const float p3 = __expf(s3 - m_new);
            float tsum = p0 + p1 + p2 + p3;
#pragma unroll
            for (int o = 8; o > 0; o >>= 1)
                tsum += __shfl_xor_sync(0xffffffffu, tsum, o);
            lrow[i] = lrow[i] * scale + tsum;

#pragma unroll
            for (int j = 0; j < 4; j++) o4[i][j] *= scale;

            float* prow = &sP[r * 68 + tx * 4];
            prow[0] = p0; prow[1] = p1; prow[2] = p2; prow[3] = p3;
        }
        __syncthreads();

#pragma unroll
        for (int kk = 0; kk < 64; kk++) {
            const float4 vv = *(const float4*)&sV[kk * 68 + tx * 4];
            const float pr[4] = {sP[(ty * 4 + 0) * 68 + kk],
                                 sP[(ty * 4 + 1) * 68 + kk],
                                 sP[(ty * 4 + 2) * 68 + kk],
                                 sP[(ty * 4 + 3) * 68 + kk]};
            const float vr[4] = {vv.x, vv.y, vv.z, vv.w};
#pragma unroll
            for (int i = 0; i < 4; i++)
#pragma unroll
                for (int j = 0; j < 4; j++)
                    o4[i][j] = fmaf(pr[i], vr[j], o4[i][j]);
        }
    }

#pragma unroll
    for (int i = 0; i < 4; i++) {
        const float inv = 1.0f / lrow[i];
        const int n = qt * 64 + ty * 4 + i;
        float4 res;
        res.x = o4[i][0] * inv; res.y = o4[i][1] * inv;
        res.z = o4[i][2] * inv; res.w = o4[i][3] * inv;
        *(float4*)&g_att[((size_t)b * GN + n) * 1024 + h * 64 + tx * 4] = res;
    }
}

// ---------------------------------------------------------------------------
extern "C" void kernel_launch(void* const* d_in, const int* in_sizes, int n_in,
                              void* d_out, int out_size) {
    (void)in_sizes; (void)n_in; (void)out_size;
    const float* queries = (const float*)d_in[0];
    const float* keys    = (const float*)d_in[1];
    const float* values  = (const float*)d_in[2];
    const float* boxes   = (const float*)d_in[3];
    const float* Wq = (const float*)d_in[4];
    const float* bq = (const float*)d_in[5];
    const float* Wk = (const float*)d_in[6];
    const float* bk = (const float*)d_in[7];
    const float* Wv = (const float*)d_in[8];
    const float* bv = (const float*)d_in[9];
    const float* Wo = (const float*)d_in[10];
    const float* bo = (const float*)d_in[11];
    const float* Wg = (const float*)d_in[12];
    const float* bg = (const float*)d_in[13];
    float* out = (float*)d_out;

    cudaFuncSetAttribute(attn_kernel, cudaFuncAttributeMaxDynamicSharedMemorySize,
                         ATTN_SMEM_BYTES);

    qkv_gemm_kernel<<<dim3(8, 32, 3), 256>>>(queries, keys, values, Wq, Wk, Wv, bq, bk, bv);
    geom_bias_kernel<<<dim3(256, 8), 256>>>(boxes, Wg, bg);
    attn_kernel<<<dim3(8, 16, 8), 256, ATTN_SMEM_BYTES>>>();
    out_gemm_kernel<<<dim3(8, 32, 1), 256>>>(Wo, bo, out);
}

// round 12
// speedup vs baseline: 3.0411x; 1.6007x over previous
#include <cuda_runtime.h>
#include <math.h>

// Problem constants
#define GB 8
#define GH 16
#define GN 512
#define GD 64
#define DMODEL 1024

// Scratch (device globals; allocation-free rule)
__device__ float g_qkv[3][(size_t)GB * GH * GN * GD];        // (z,b,h,n,d)
__device__ float g_geob[(size_t)GB * GH * GN * GN];          // (b,h,i,j)  log(max(g,1e-6))
__device__ float g_att[(size_t)GB * GN * GH * GD];           // (b,n,h*64+d)

// ---------------------------------------------------------------------------
// SGEMM (unchanged — pipelined ping-pong, one sync per chunk)
// ---------------------------------------------------------------------------
template <int PERM>
__device__ __forceinline__ void sgemm_body(const float* __restrict__ A,
                                           const float* __restrict__ W,
                                           const float* __restrict__ bias,
                                           float* __restrict__ C) {
    constexpr int LDS = 132;  // 128 + 4 pad
    __shared__ float As[2][8 * LDS];
    __shared__ float Ws[2][8 * LDS];

    const int tid = threadIdx.x;
    const int tx = tid & 15;
    const int ty = tid >> 4;
    const int rowBase = blockIdx.y * 128;
    const int colBase = blockIdx.x * 128;
    const int lrow = tid >> 1;        // 0..127
    const int lk = (tid & 1) * 4;     // 0 or 4

    const float* Ag = A + (size_t)(rowBase + lrow) * 1024 + lk;
    const float* Wg = W + (size_t)(colBase + lrow) * 1024 + lk;

    float acc[8][8];
#pragma unroll
    for (int i = 0; i < 8; i++)
#pragma unroll
        for (int j = 0; j < 8; j++) acc[i][j] = 0.f;

#define SGEMM_STS(buf, a4, w4)                        \
    As[buf][(lk + 0) * LDS + lrow] = a4.x;            \
    As[buf][(lk + 1) * LDS + lrow] = a4.y;            \
    As[buf][(lk + 2) * LDS + lrow] = a4.z;            \
    As[buf][(lk + 3) * LDS + lrow] = a4.w;            \
    Ws[buf][(lk + 0) * LDS + lrow] = w4.x;            \
    Ws[buf][(lk + 1) * LDS + lrow] = w4.y;            \
    Ws[buf][(lk + 2) * LDS + lrow] = w4.z;            \
    Ws[buf][(lk + 3) * LDS + lrow] = w4.w;

#define SGEMM_FFMA(buf)                                                        \
    _Pragma("unroll")                                                          \
    for (int kk = 0; kk < 8; kk++) {                                           \
        const float4 a0 = *(const float4*)&As[buf][kk * LDS + ty * 8];         \
        const float4 a1 = *(const float4*)&As[buf][kk * LDS + ty * 8 + 4];     \
        const float4 b0 = *(const float4*)&Ws[buf][kk * LDS + tx * 8];         \
        const float4 b1 = *(const float4*)&Ws[buf][kk * LDS + tx * 8 + 4];     \
        const float ar[8] = {a0.x, a0.y, a0.z, a0.w, a1.x, a1.y, a1.z, a1.w};  \
        const float br[8] = {b0.x, b0.y, b0.z, b0.w, b1.x, b1.y, b1.z, b1.w};  \
        _Pragma("unroll")                                                      \
        for (int i = 0; i < 8; i++)                                            \
            _Pragma("unroll")                                                  \
            for (int j = 0; j < 8; j++)                                        \
                acc[i][j] = fmaf(ar[i], br[j], acc[i][j]);                     \
    }

    // prefetch chunk 0
    float4 av = *(const float4*)(Ag);
    float4 wv = *(const float4*)(Wg);

#pragma unroll 1
    for (int c = 0; c < 128; c += 2) {
        SGEMM_STS(0, av, wv)
        {
            const int kn = (c + 1 < 127 ? c + 1 : 127) * 8;
            av = *(const float4*)(Ag + kn);
            wv = *(const float4*)(Wg + kn);
        }
        __syncthreads();
        SGEMM_FFMA(0)

        SGEMM_STS(1, av, wv)
        {
            const int kn = (c + 2 < 127 ? c + 2 : 127) * 8;
            av = *(const float4*)(Ag + kn);
            wv = *(const float4*)(Wg + kn);
        }
        __syncthreads();
        SGEMM_FFMA(1)
    }
#undef SGEMM_STS
#undef SGEMM_FFMA

#pragma unroll
    for (int i = 0; i < 8; i++) {
        const int r = rowBase + ty * 8 + i;
#pragma unroll
        for (int j = 0; j < 8; j++) {
            const int c = colBase + tx * 8 + j;
            const float val = acc[i][j] + bias[c];
            if (PERM) {
                const int bb = r >> 9, n = r & 511;
                const int h = c >> 6, d = c & 63;
                C[(((size_t)(bb * GH + h) * GN + n) << 6) + d] = val;
            } else {
                C[(size_t)r * 1024 + c] = val;
            }
        }
    }
}

__global__ __launch_bounds__(256, 2) void qkv_gemm_kernel(
    const float* __restrict__ q, const float* __restrict__ k, const float* __restrict__ v,
    const float* __restrict__ Wq, const float* __restrict__ Wk, const float* __restrict__ Wv,
    const float* __restrict__ bq, const float* __restrict__ bk, const float* __restrict__ bv) {
    const int z = blockIdx.z;
    const float* A = (z == 0) ? q : (z == 1) ? k : v;
    const float* W = (z == 0) ? Wq : (z == 1) ? Wk : Wv;
    const float* bs = (z == 0) ? bq : (z == 1) ? bk : bv;
    sgemm_body<1>(A, W, bs, g_qkv[z]);
}

__global__ __launch_bounds__(256, 2) void out_gemm_kernel(
    const float* __restrict__ Wo, const float* __restrict__ bo, float* __restrict__ out) {
    sgemm_body<0>(g_att, Wo, bo, out);
}

// ---------------------------------------------------------------------------
// Geometry bias, register-tiled (unchanged from R11 win)
// ---------------------------------------------------------------------------
__global__ __launch_bounds__(256, 2) void geom_bias_kernel(const float* __restrict__ boxes,
                                                           const float* __restrict__ Wgm,
                                                           const float* __restrict__ bgv) {
    __shared__ float scx[512], scy[512], siw[512], sih[512], slw[512], slh[512];
    __shared__ float2 sW2[512];   // [(p*8+f)*16 + h] = (W_sin, W_cos)
    __shared__ float sbg[16];

    const int tid = threadIdx.x;
    const int b = blockIdx.y;
    const int i = blockIdx.x * 2 + (tid >> 7);   // 2 i's per block
    const int jt = tid & 127;                    // base j; handles jt + {0,128,256,384}

    for (int j = tid; j < 512; j += 256) {
        const float4 bx = *(const float4*)&boxes[((size_t)b * 512 + j) * 4];
        const float cx = (bx.x + bx.z) * 0.5f;
        const float cy = (bx.y + bx.w) * 0.5f;
        const float w = (bx.z - bx.x) + 1.0f;
        const float hh = (bx.w - bx.y) + 1.0f;
        scx[j] = cx; scy[j] = cy;
        siw[j] = w;  sih[j] = hh;
        slw[j] = __logf(w); slh[j] = __logf(hh);
    }
    for (int t = tid; t < 512; t += 256) {
        const int pf = t >> 4, h = t & 15;
        sW2[t] = make_float2(Wgm[h * 64 + pf], Wgm[h * 64 + 32 + pf]);
    }
    if (tid < 16) sbg[tid] = bgv[tid];
    __syncthreads();

    const float cxi = scx[i], cyi = scy[i];
    const float inv_wi = 1.0f / siw[i], inv_hi = 1.0f / sih[i];
    const float lwi = slw[i], lhi = slh[i];

    const float dimc[8] = {1.0f, 0.421696503f, 0.177827941f, 0.0749894209f,
                           0.0316227766f, 0.0133352143f, 0.00562341325f, 0.00237137371f};

    float pos[4][4];
#pragma unroll
    for (int jj = 0; jj < 4; jj++) {
        const int j = jt + jj * 128;
        pos[0][jj] = __logf(fmaxf(fabsf(cxi - scx[j]) * inv_wi, 1e-3f));
        pos[1][jj] = __logf(fmaxf(fabsf(cyi - scy[j]) * inv_hi, 1e-3f));
        pos[2][jj] = lwi - slw[j];
        pos[3][jj] = lhi - slh[j];
    }

    float acc[4][16];
#pragma unroll
    for (int jj = 0; jj < 4; jj++)
#pragma unroll
        for (int h = 0; h < 16; h++) acc[jj][h] = sbg[h];

#pragma unroll
    for (int p = 0; p < 4; p++) {
#pragma unroll
        for (int f = 0; f < 8; f++) {
            float s[4], c[4];
#pragma unroll
            for (int jj = 0; jj < 4; jj++)
                __sincosf(100.0f * pos[p][jj] * dimc[f], &s[jj], &c[jj]);
            const float2* wrow = &sW2[(p * 8 + f) * 16];
#pragma unroll
            for (int h = 0; h < 16; h++) {
                const float2 w2 = wrow[h];   // broadcast across warp
#pragma unroll
                for (int jj = 0; jj < 4; jj++)
                    acc[jj][h] = fmaf(s[jj], w2.x, fmaf(c[jj], w2.y, acc[jj][h]));
            }
        }
    }

#pragma unroll
    for (int h = 0; h < 16; h++) {
        float* dst = &g_geob[(((size_t)(b * GH + h) * GN + i) * GN) + jt];
#pragma unroll
        for (int jj = 0; jj < 4; jj++)
            dst[jj * 128] = __logf(fmaxf(acc[jj][h], 1e-6f));
    }
}

// ---------------------------------------------------------------------------
// Flash-style attention, retiled: 128-query CTA, 8x4 micro-tile per thread.
// LDS bytes/FMA: 2.0 -> 1.5; per-element barrier cost halved.
// smem: sQ 64x132 + sK 64x68 + sV 64x68 + sP 128x68 = 103,424 B -> 2 CTAs/SM.
// ---------------------------------------------------------------------------
#define ATTN_SMEM_BYTES ((64 * 132 + 2 * 64 * 68 + 128 * 68) * 4)

__global__ __launch_bounds__(256, 2) void attn_kernel() {
    extern __shared__ float sm[];
    float* sQ = sm;                        // [d][r], stride 132 (128 rows)
    float* sK = sQ + 64 * 132;             // [d][j], stride 68
    float* sV = sK + 64 * 68;              // [j][d], stride 68
    float* sP = sV + 64 * 68;              // [r][j], stride 68 (128 rows)

    const int tid = threadIdx.x;
    const int qt = blockIdx.x, h = blockIdx.y, b = blockIdx.z;
    const int bh = b * GH + h;
    const float* qb = g_qkv[0] + ((size_t)bh * GN + qt * 128) * GD;
    const float* kb = g_qkv[1] + (size_t)bh * GN * GD;
    const float* vb = g_qkv[2] + (size_t)bh * GN * GD;
    const float* gb = g_geob + ((size_t)bh * GN + qt * 128) * GN;

    // Load Q tile (128 rows x 64 d) transposed
#pragma unroll
    for (int t = tid; t < 8192; t += 256) {
        const int r = t >> 6, d = t & 63;
        sQ[d * 132 + r] = qb[t];
    }

    const int tx = tid & 15;   // 16 col groups (4 cols each)
    const int ty = tid >> 4;   // 16 row groups (8 rows each)

    float mrow[8], lrow[8], o4[8][4];
#pragma unroll
    for (int i = 0; i < 8; i++) {
        mrow[i] = -1e30f;
        lrow[i] = 0.f;
#pragma unroll
        for (int j = 0; j < 4; j++) o4[i][j] = 0.f;
    }

    for (int jt = 0; jt < 8; jt++) {
        __syncthreads();   // prev PV reads of sK/sV/sP done
#pragma unroll
        for (int t = tid; t < 4096; t += 256) {
            const int r = t >> 6, d = t & 63;
            sK[d * 68 + r] = kb[jt * 4096 + t];
        }
#pragma unroll
        for (int t = tid; t < 4096; t += 256) {
            const int r = t >> 6, d = t & 63;
            sV[r * 68 + d] = vb[jt * 4096 + t];
        }
        __syncthreads();

        // s = Q K^T for this tile (8 rows x 4 cols per thread)
        float acc[8][4];
#pragma unroll
        for (int i = 0; i < 8; i++)
#pragma unroll
            for (int j = 0; j < 4; j++) acc[i][j] = 0.f;
#pragma unroll
        for (int d = 0; d < 64; d++) {
            const float4 a0 = *(const float4*)&sQ[d * 132 + ty * 8];
            const float4 a1 = *(const float4*)&sQ[d * 132 + ty * 8 + 4];
            const float4 kv = *(const float4*)&sK[d * 68 + tx * 4];
            const float ar[8] = {a0.x, a0.y, a0.z, a0.w, a1.x, a1.y, a1.z, a1.w};
            const float br[4] = {kv.x, kv.y, kv.z, kv.w};
#pragma unroll
            for (int i = 0; i < 8; i++)
#pragma unroll
                for (int j = 0; j < 4; j++)
                    acc[i][j] = fmaf(ar[i], br[j], acc[i][j]);
        }

        // s = s/8 + bias; online softmax update; stage P in smem
#pragma unroll
        for (int i = 0; i < 8; i++) {
            const int r = ty * 8 + i;
            const float4 b4 = *(const float4*)&gb[(size_t)r * GN + jt * 64 + tx * 4];
            float s0 = fmaf(acc[i][0], 0.125f, b4.x);
            float s1 = fmaf(acc[i][1], 0.125f, b4.y);
            float s2 = fmaf(acc[i][2], 0.125f, b4.z);
            float s3 = fmaf(acc[i][3], 0.125f, b4.w);

            float tmax = fmaxf(fmaxf(s0, s1), fmaxf(s2, s3));
#pragma unroll
            for (int o = 8; o > 0; o >>= 1)
                tmax = fmaxf(tmax, __shfl_xor_sync(0xffffffffu, tmax, o));
            const float m_new = fmaxf(mrow[i], tmax);
            const float scale = __expf(mrow[i] - m_new);
            mrow[i] = m_new;

            const float p0 = __expf(s0 - m_new);
            const float p1 = __expf(s1 - m_new);
            const float p2 = __expf(s2 - m_new);
            const float p3 = __expf(s3 - m_new);
            float tsum = p0 + p1 + p2 + p3;
#pragma unroll
            for (int o = 8; o > 0; o >>= 1)
                tsum += __shfl_xor_sync(0xffffffffu, tsum, o);
            lrow[i] = lrow[i] * scale + tsum;

#pragma unroll
            for (int j = 0; j < 4; j++) o4[i][j] *= scale;

            float4 pv;
            pv.x = p0; pv.y = p1; pv.z = p2; pv.w = p3;
            *(float4*)&sP[r * 68 + tx * 4] = pv;
        }
        __syncthreads();

        // O += P V  (this tile)
#pragma unroll 4
        for (int kk = 0; kk < 64; kk++) {
            const float4 vv = *(const float4*)&sV[kk * 68 + tx * 4];
            const float vr[4] = {vv.x, vv.y, vv.z, vv.w};
#pragma unroll
            for (int i = 0; i < 8; i++) {
                const float p = sP[(ty * 8 + i) * 68 + kk];
#pragma unroll
                for (int j = 0; j < 4; j++)
                    o4[i][j] = fmaf(p, vr[j], o4[i][j]);
            }
        }
    }

    // Normalize and store to (b, n, h*64+d)
#pragma unroll
    for (int i = 0; i < 8; i++) {
        const float inv = 1.0f / lrow[i];
        const int n = qt * 128 + ty * 8 + i;
        float4 res;
        res.x = o4[i][0] * inv; res.y = o4[i][1] * inv;
        res.z = o4[i][2] * inv; res.w = o4[i][3] * inv;
        *(float4*)&g_att[((size_t)b * GN + n) * 1024 + h * 64 + tx * 4] = res;
    }
}

// ---------------------------------------------------------------------------
extern "C" void kernel_launch(void* const* d_in, const int* in_sizes, int n_in,
                              void* d_out, int out_size) {
    (void)in_sizes; (void)n_in; (void)out_size;
    const float* queries = (const float*)d_in[0];
    const float* keys    = (const float*)d_in[1];
    const float* values  = (const float*)d_in[2];
    const float* boxes   = (const float*)d_in[3];
    const float* Wq = (const float*)d_in[4];
    const float* bq = (const float*)d_in[5];
    const float* Wk = (const float*)d_in[6];
    const float* bk = (const float*)d_in[7];
    const float* Wv = (const float*)d_in[8];
    const float* bv = (const float*)d_in[9];
    const float* Wo = (const float*)d_in[10];
    const float* bo = (const float*)d_in[11];
    const float* Wg = (const float*)d_in[12];
    const float* bg = (const float*)d_in[13];
    float* out = (float*)d_out;

    cudaFuncSetAttribute(attn_kernel, cudaFuncAttributeMaxDynamicSharedMemorySize,
                         ATTN_SMEM_BYTES);

    qkv_gemm_kernel<<<dim3(8, 32, 3), 256>>>(queries, keys, values, Wq, Wk, Wv, bq, bk, bv);
    geom_bias_kernel<<<dim3(256, 8), 256>>>(boxes, Wg, bg);
    attn_kernel<<<dim3(4, 16, 8), 256, ATTN_SMEM_BYTES>>>();
    out_gemm_kernel<<<dim3(8, 32, 1), 256>>>(Wo, bo, out);
}

// round 16
// speedup vs baseline: 4.5427x; 1.4938x over previous
#include <cuda_runtime.h>
#include <cuda_bf16.h>
#include <math.h>
#include <stdint.h>

// Problem constants
#define GB 8
#define GH 16
#define GN 512
#define GD 64

// Scratch (device globals; allocation-free rule)
__device__ float g_qkv[3][(size_t)GB * GH * GN * GD];        // (z,b,h,n,d)
__device__ float g_geob[(size_t)GB * GH * GN * GN];          // (b,h,i,j)  log(max(g,1e-6))
__device__ float g_att[(size_t)GB * GN * GH * GD];           // (b,n,h*64+d)

// ===========================================================================
// Helpers
// ===========================================================================
__device__ __forceinline__ uint32_t smem_u32(const void* p) {
    uint32_t a;
    asm("{ .reg .u64 t; cvta.to.shared.u64 t, %1; cvt.u32.u64 %0, t; }" : "=r"(a) : "l"(p));
    return a;
}

// split 2 floats into packed bf16 hi pair + bf16 lo (residual) pair
__device__ __forceinline__ void split2(float x, float y, uint32_t& h, uint32_t& l) {
    uint32_t hh;
    asm("cvt.rn.bf16x2.f32 %0, %1, %2;" : "=r"(hh) : "f"(y), "f"(x));  // hi=y, lo=x
    const float bx = __uint_as_float(hh << 16);
    const float by = __uint_as_float(hh & 0xFFFF0000u);
    const float lx = x - bx, ly = y - by;
    asm("cvt.rn.bf16x2.f32 %0, %1, %2;" : "=r"(l) : "f"(ly), "f"(lx));
    h = hh;
}

__device__ __forceinline__ void split_sts4(const float4 v, __nv_bfloat16* hp,
                                           __nv_bfloat16* lp) {
    uint2 h, l;
    split2(v.x, v.y, h.x, l.x);
    split2(v.z, v.w, h.y, l.y);
    *(uint2*)hp = h;
    *(uint2*)lp = l;
}

#define LDSM4(r, addr)                                                        \
    asm volatile("ldmatrix.sync.aligned.m8n8.x4.shared.b16 {%0,%1,%2,%3}, [%4];" \
                 : "=r"((r)[0]), "=r"((r)[1]), "=r"((r)[2]), "=r"((r)[3])     \
                 : "r"(addr))

#define MMA16816(c, a, b0, b1)                                                \
    asm volatile(                                                             \
        "mma.sync.aligned.m16n8k16.row.col.f32.bf16.bf16.f32 "                \
        "{%0,%1,%2,%3}, {%4,%5,%6,%7}, {%8,%9}, {%0,%1,%2,%3};"               \
        : "+f"((c)[0]), "+f"((c)[1]), "+f"((c)[2]), "+f"((c)[3])              \
        : "r"((a)[0]), "r"((a)[1]), "r"((a)[2]), "r"((a)[3]), "r"(b0), "r"(b1))

// ===========================================================================
// HMMA GEMM: C[m][c] = sum_k A[m][k] * W[c][k] + bias[c]
// M=4096, N=1024, K=1024. CTA 128x128, 8 warps (64x32 each), K-chunks of 64.
// bf16 hi/lo split: D = Ah*Wh + Ah*Wl + Al*Wh, fp32 accum in registers.
// smem: 4 bf16 tiles 128x72 (pad) = 73,728 B dynamic -> 2 CTAs/SM.
// ===========================================================================
#define MMA_SMEM_BYTES (4 * 128 * 72 * 2)
#define KST 72   // bf16 elements per padded row (144 B, 16B-multiple for ldmatrix)

template <int PERM>
__device__ __forceinline__ void mma_gemm_body(const float* __restrict__ A,
                                              const float* __restrict__ W,
                                              const float* __restrict__ bias,
                                              float* __restrict__ C) {
    extern __shared__ __nv_bfloat16 dsm[];
    __nv_bfloat16* sAh = dsm;
    __nv_bfloat16* sAl = dsm + 128 * KST;
    __nv_bfloat16* sBh = dsm + 2 * 128 * KST;
    __nv_bfloat16* sBl = dsm + 3 * 128 * KST;

    const int tid = threadIdx.x;
    const int wid = tid >> 5, lane = tid & 31;
    const int rowBase = blockIdx.y * 128;
    const int colBase = blockIdx.x * 128;
    const int lr = tid >> 1;            // 0..127: smem row this thread fills
    const int khalf = (tid & 1) * 32;   // half of the 64-wide K chunk
    const float* Ag = A + (size_t)(rowBase + lr) * 1024 + khalf;
    const float* Wg = W + (size_t)(colBase + lr) * 1024 + khalf;

    const int warpM = (wid >> 2) * 64;  // 2 warp-rows
    const int warpN = (wid & 3) * 32;   // 4 warp-cols

    float acc[4][4][4];
#pragma unroll
    for (int mt = 0; mt < 4; mt++)
#pragma unroll
        for (int nt = 0; nt < 4; nt++)
#pragma unroll
            for (int e = 0; e < 4; e++) acc[mt][nt][e] = 0.f;

    // ldmatrix lane address patterns (A: m16xk16 x4; B: n16xk16 x4)
    const int aRow = lane & 15;                       // rows 0-15
    const int aK = (lane >> 4) * 8;                   // k 0 / 8
    const int bRow = ((lane >> 4) << 3) + (lane & 7); // n 0-7 then 8-15
    const int bK = ((lane >> 3) & 1) * 8;             // k 0 / 8
    const uint32_t aOffH = smem_u32(sAh) + (uint32_t)(((warpM + aRow) * KST + aK) << 1);
    const uint32_t aOffL = smem_u32(sAl) + (uint32_t)(((warpM + aRow) * KST + aK) << 1);
    const uint32_t bOffH = smem_u32(sBh) + (uint32_t)(((warpN + bRow) * KST + bK) << 1);
    const uint32_t bOffL = smem_u32(sBl) + (uint32_t)(((warpN + bRow) * KST + bK) << 1);

    const uint32_t sts = (uint32_t)(lr * KST + khalf);

#pragma unroll 1
    for (int kc = 0; kc < 16; kc++) {
        float4 av[8], wv[8];
#pragma unroll
        for (int f = 0; f < 8; f++) {
            av[f] = *(const float4*)(Ag + kc * 64 + f * 4);
            wv[f] = *(const float4*)(Wg + kc * 64 + f * 4);
        }
        __syncthreads();  // prior MMA-phase ldmatrix reads complete
#pragma unroll
        for (int f = 0; f < 8; f++) {
            split_sts4(av[f], sAh + sts + f * 4, sAl + sts + f * 4);
            split_sts4(wv[f], sBh + sts + f * 4, sBl + sts + f * 4);
        }
        __syncthreads();

#pragma unroll
        for (int ks = 0; ks < 4; ks++) {
            const uint32_t ko = (uint32_t)(ks * 16) << 1;
            uint32_t bh[2][4], bl[2][4];
            LDSM4(bh[0], bOffH + ko);
            LDSM4(bh[1], bOffH + (16 * KST * 2) + ko);
            LDSM4(bl[0], bOffL + ko);
            LDSM4(bl[1], bOffL + (16 * KST * 2) + ko);
#pragma unroll
            for (int mt = 0; mt < 4; mt++) {
                uint32_t ah[4], al[4];
                LDSM4(ah, aOffH + (uint32_t)(mt * 16 * KST * 2) + ko);
                LDSM4(al, aOffL + (uint32_t)(mt * 16 * KST * 2) + ko);
#pragma unroll
                for (int nt = 0; nt < 4; nt++) {
                    const int h2 = nt >> 1, p2 = (nt & 1) * 2;
                    MMA16816(acc[mt][nt], ah, bh[h2][p2], bh[h2][p2 + 1]);
                    MMA16816(acc[mt][nt], ah, bl[h2][p2], bl[h2][p2 + 1]);
                    MMA16816(acc[mt][nt], al, bh[h2][p2], bh[h2][p2 + 1]);
                }
            }
        }
    }

    // Epilogue: frag (m16n8): c0,c1 -> (row g, col 2t/2t+1); c2,c3 -> row g+8.
    const int g = lane >> 2;
    const int t2 = (lane & 3) * 2;
#pragma unroll
    for (int mt = 0; mt < 4; mt++) {
#pragma unroll
        for (int nt = 0; nt < 4; nt++) {
            const int c0 = colBase + warpN + nt * 8 + t2;
            const float bx = bias[c0], by = bias[c0 + 1];
#pragma unroll
            for (int half = 0; half < 2; half++) {
                const int m = rowBase + warpM + mt * 16 + g + half * 8;
                float2 res;
                res.x = acc[mt][nt][half * 2 + 0] + bx;
                res.y = acc[mt][nt][half * 2 + 1] + by;
                if (PERM) {
                    const int bb = m >> 9, n = m & 511;
                    const int hh = c0 >> 6, d = c0 & 63;
                    *(float2*)&C[(((size_t)(bb * GH + hh) * GN + n) << 6) + d] = res;
                } else {
                    *(float2*)&C[(size_t)m * 1024 + c0] = res;
                }
            }
        }
    }
}

__global__ __launch_bounds__(256, 2) void mma_qkv_kernel(
    const float* __restrict__ q, const float* __restrict__ k, const float* __restrict__ v,
    const float* __restrict__ Wq, const float* __restrict__ Wk, const float* __restrict__ Wv,
    const float* __restrict__ bq, const float* __restrict__ bk, const float* __restrict__ bv) {
    const int z = blockIdx.z;
    const float* A = (z == 0) ? q : (z == 1) ? k : v;
    const float* W = (z == 0) ? Wq : (z == 1) ? Wk : Wv;
    const float* bs = (z == 0) ? bq : (z == 1) ? bk : bv;
    mma_gemm_body<1>(A, W, bs, g_qkv[z]);
}

__global__ __launch_bounds__(256, 2) void mma_out_kernel(
    const float* __restrict__ Wo, const float* __restrict__ bo, float* __restrict__ out) {
    mma_gemm_body<0>(g_att, Wo, bo, out);
}

// ---------------------------------------------------------------------------
// Geometry bias, register-tiled (unchanged from R11 win)
// ---------------------------------------------------------------------------
__global__ __launch_bounds__(256, 2) void geom_bias_kernel(const float* __restrict__ boxes,
                                                           const float* __restrict__ Wgm,
                                                           const float* __restrict__ bgv) {
    __shared__ float scx[512], scy[512], siw[512], sih[512], slw[512], slh[512];
    __shared__ float2 sW2[512];   // [(p*8+f)*16 + h] = (W_sin, W_cos)
    __shared__ float sbg[16];

    const int tid = threadIdx.x;
    const int b = blockIdx.y;
    const int i = blockIdx.x * 2 + (tid >> 7);
    const int jt = tid & 127;

    for (int j = tid; j < 512; j += 256) {
        const float4 bx = *(const float4*)&boxes[((size_t)b * 512 + j) * 4];
        const float cx = (bx.x + bx.z) * 0.5f;
        const float cy = (bx.y + bx.w) * 0.5f;
        const float w = (bx.z - bx.x) + 1.0f;
        const float hh = (bx.w - bx.y) + 1.0f;
        scx[j] = cx; scy[j] = cy;
        siw[j] = w;  sih[j] = hh;
        slw[j] = __logf(w); slh[j] = __logf(hh);
    }
    for (int t = tid; t < 512; t += 256) {
        const int pf = t >> 4, h = t & 15;
        sW2[t] = make_float2(Wgm[h * 64 + pf], Wgm[h * 64 + 32 + pf]);
    }
    if (tid < 16) sbg[tid] = bgv[tid];
    __syncthreads();

    const float cxi = scx[i], cyi = scy[i];
    const float inv_wi = 1.0f / siw[i], inv_hi = 1.0f / sih[i];
    const float lwi = slw[i], lhi = slh[i];

    const float dimc[8] = {1.0f, 0.421696503f, 0.177827941f, 0.0749894209f,
                           0.0316227766f, 0.0133352143f, 0.00562341325f, 0.00237137371f};

    float pos[4][4];
#pragma unroll
    for (int jj = 0; jj < 4; jj++) {
        const int j = jt + jj * 128;
        pos[0][jj] = __logf(fmaxf(fabsf(cxi - scx[j]) * inv_wi, 1e-3f));
        pos[1][jj] = __logf(fmaxf(fabsf(cyi - scy[j]) * inv_hi, 1e-3f));
        pos[2][jj] = lwi - slw[j];
        pos[3][jj] = lhi - slh[j];
    }

    float acc[4][16];
#pragma unroll
    for (int jj = 0; jj < 4; jj++)
#pragma unroll
        for (int h = 0; h < 16; h++) acc[jj][h] = sbg[h];

#pragma unroll
    for (int p = 0; p < 4; p++) {
#pragma unroll
        for (int f = 0; f < 8; f++) {
            float s[4], c[4];
#pragma unroll
            for (int jj = 0; jj < 4; jj++)
                __sincosf(100.0f * pos[p][jj] * dimc[f], &s[jj], &c[jj]);
            const float2* wrow = &sW2[(p * 8 + f) * 16];
#pragma unroll
            for (int h = 0; h < 16; h++) {
                const float2 w2 = wrow[h];
#pragma unroll
                for (int jj = 0; jj < 4; jj++)
                    acc[jj][h] = fmaf(s[jj], w2.x, fmaf(c[jj], w2.y, acc[jj][h]));
            }
        }
    }

#pragma unroll
    for (int h = 0; h < 16; h++) {
        float* dst = &g_geob[(((size_t)(b * GH + h) * GN + i) * GN) + jt];
#pragma unroll
        for (int jj = 0; jj < 4; jj++)
            dst[jj * 128] = __logf(fmaxf(acc[jj][h], 1e-6f));
    }
}

// ---------------------------------------------------------------------------
// Flash-style attention (unchanged from R12 win): 128-query CTA, 8x4 tile.
// ---------------------------------------------------------------------------
#define ATTN_SMEM_BYTES ((64 * 132 + 2 * 64 * 68 + 128 * 68) * 4)

__global__ __launch_bounds__(256, 2) void attn_kernel() {
    extern __shared__ float sm[];
    float* sQ = sm;                        // [d][r], stride 132 (128 rows)
    float* sK = sQ + 64 * 132;             // [d][j], stride 68
    float* sV = sK + 64 * 68;              // [j][d], stride 68
    float* sP = sV + 64 * 68;              // [r][j], stride 68 (128 rows)

    const int tid = threadIdx.x;
    const int qt = blockIdx.x, h = blockIdx.y, b = blockIdx.z;
    const int bh = b * GH + h;
    const float* qb = g_qkv[0] + ((size_t)bh * GN + qt * 128) * GD;
    const float* kb = g_qkv[1] + (size_t)bh * GN * GD;
    const float* vb = g_qkv[2] + (size_t)bh * GN * GD;
    const float* gb = g_geob + ((size_t)bh * GN + qt * 128) * GN;

#pragma unroll
    for (int t = tid; t < 8192; t += 256) {
        const int r = t >> 6, d = t & 63;
        sQ[d * 132 + r] = qb[t];
    }

    const int tx = tid & 15;
    const int ty = tid >> 4;

    float mrow[8], lrow[8], o4[8][4];
#pragma unroll
    for (int i = 0; i < 8; i++) {
        mrow[i] = -1e30f;
        lrow[i] = 0.f;
#pragma unroll
        for (int j = 0; j < 4; j++) o4[i][j] = 0.f;
    }

    for (int jt = 0; jt < 8; jt++) {
        __syncthreads();
#pragma unroll
        for (int t = tid; t < 4096; t += 256) {
            const int r = t >> 6, d = t & 63;
            sK[d * 68 + r] = kb[jt * 4096 + t];
        }
#pragma unroll
        for (int t = tid; t < 4096; t += 256) {
            const int r = t >> 6, d = t & 63;
            sV[r * 68 + d] = vb[jt * 4096 + t];
        }
        __syncthreads();

        float acc[8][4];
#pragma unroll
        for (int i = 0; i < 8; i++)
#pragma unroll
            for (int j = 0; j < 4; j++) acc[i][j] = 0.f;
#pragma unroll
        for (int d = 0; d < 64; d++) {
            const float4 a0 = *(const float4*)&sQ[d * 132 + ty * 8];
            const float4 a1 = *(const float4*)&sQ[d * 132 + ty * 8 + 4];
            const float4 kv = *(const float4*)&sK[d * 68 + tx * 4];
            const float ar[8] = {a0.x, a0.y, a0.z, a0.w, a1.x, a1.y, a1.z, a1.w};
            const float br[4] = {kv.x, kv.y, kv.z, kv.w};
#pragma unroll
            for (int i = 0; i < 8; i++)
#pragma unroll
                for (int j = 0; j < 4; j++)
                    acc[i][j] = fmaf(ar[i], br[j], acc[i][j]);
        }

#pragma unroll
        for (int i = 0; i < 8; i++) {
            const int r = ty * 8 + i;
            const float4 b4 = *(const float4*)&gb[(size_t)r * GN + jt * 64 + tx * 4];
            float s0 = fmaf(acc[i][0], 0.125f, b4.x);
            float s1 = fmaf(acc[i][1], 0.125f, b4.y);
            float s2 = fmaf(acc[i][2], 0.125f, b4.z);
            float s3 = fmaf(acc[i][3], 0.125f, b4.w);

            float tmax = fmaxf(fmaxf(s0, s1), fmaxf(s2, s3));
#pragma unroll
            for (int o = 8; o > 0; o >>= 1)
                tmax = fmaxf(tmax, __shfl_xor_sync(0xffffffffu, tmax, o));
            const float m_new = fmaxf(mrow[i], tmax);
            const float scale = __expf(mrow[i] - m_new);
            mrow[i] = m_new;

            const float p0 = __expf(s0 - m_new);
            const float p1 = __expf(s1 - m_new);
            const float p2 = __expf(s2 - m_new);
            const float p3 = __expf(s3 - m_new);
            float tsum = p0 + p1 + p2 + p3;
#pragma unroll
            for (int o = 8; o > 0; o >>= 1)
                tsum += __shfl_xor_sync(0xffffffffu, tsum, o);
            lrow[i] = lrow[i] * scale + tsum;

#pragma unroll
            for (int j = 0; j < 4; j++) o4[i][j] *= scale;

            float4 pv;
            pv.x = p0; pv.y = p1; pv.z = p2; pv.w = p3;
            *(float4*)&sP[r * 68 + tx * 4] = pv;
        }
        __syncthreads();

#pragma unroll 4
        for (int kk = 0; kk < 64; kk++) {
            const float4 vv = *(const float4*)&sV[kk * 68 + tx * 4];
            const float vr[4] = {vv.x, vv.y, vv.z, vv.w};
#pragma unroll
            for (int i = 0; i < 8; i++) {
                const float p = sP[(ty * 8 + i) * 68 + kk];
#pragma unroll
                for (int j = 0; j < 4; j++)
                    o4[i][j] = fmaf(p, vr[j], o4[i][j]);
            }
        }
    }

#pragma unroll
    for (int i = 0; i < 8; i++) {
        const float inv = 1.0f / lrow[i];
        const int n = qt * 128 + ty * 8 + i;
        float4 res;
        res.x = o4[i][0] * inv; res.y = o4[i][1] * inv;
        res.z = o4[i][2] * inv; res.w = o4[i][3] * inv;
        *(float4*)&g_att[((size_t)b * GN + n) * 1024 + h * 64 + tx * 4] = res;
    }
}

// ---------------------------------------------------------------------------
extern "C" void kernel_launch(void* const* d_in, const int* in_sizes, int n_in,
                              void* d_out, int out_size) {
    (void)in_sizes; (void)n_in; (void)out_size;
    const float* queries = (const float*)d_in[0];
    const float* keys    = (const float*)d_in[1];
    const float* values  = (const float*)d_in[2];
    const float* boxes   = (const float*)d_in[3];
    const float* Wq = (const float*)d_in[4];
    const float* bq = (const float*)d_in[5];
    const float* Wk = (const float*)d_in[6];
    const float* bk = (const float*)d_in[7];
    const float* Wv = (const float*)d_in[8];
    const float* bv = (const float*)d_in[9];
    const float* Wo = (const float*)d_in[10];
    const float* bo = (const float*)d_in[11];
    const float* Wg = (const float*)d_in[12];
    const float* bg = (const float*)d_in[13];
    float* out = (float*)d_out;

    cudaFuncSetAttribute(mma_qkv_kernel, cudaFuncAttributeMaxDynamicSharedMemorySize,
                         MMA_SMEM_BYTES);
    cudaFuncSetAttribute(mma_out_kernel, cudaFuncAttributeMaxDynamicSharedMemorySize,
                         MMA_SMEM_BYTES);
    cudaFuncSetAttribute(attn_kernel, cudaFuncAttributeMaxDynamicSharedMemorySize,
                         ATTN_SMEM_BYTES);

    mma_qkv_kernel<<<dim3(8, 32, 3), 256, MMA_SMEM_BYTES>>>(queries, keys, values,
                                                            Wq, Wk, Wv, bq, bk, bv);
    geom_bias_kernel<<<dim3(256, 8), 256>>>(boxes, Wg, bg);
    attn_kernel<<<dim3(4, 16, 8), 256, ATTN_SMEM_BYTES>>>();
    mma_out_kernel<<<dim3(8, 32, 1), 256, MMA_SMEM_BYTES>>>(Wo, bo, out);
}